// round 11
// baseline (speedup 1.0000x reference)
#include <cuda_runtime.h>

#define NN 100000
#define NE 1600000
#define HP 20                 // padded node feature width (19 used, [19]=0)
#define NB 391                // ceil(NN/256)
#define NE4 (NE / 4)          // 400000 int4 records exactly

typedef unsigned long long ull;

// ---------------- device scratch (static; no allocations) ----------------
__device__ __align__(16) float  g_h[NN * HP];     // node state [N,20]
__device__ float4 g_A[NN * 4];                    // h @ eW1_top + eb1
__device__ float4 g_B[NN * 4];                    // h @ eW1_bot
__device__ float4 g_C[NN * 4];                    // h @ msgW1_bot (node/out)
__device__ float4 g_macc[NN * 4];                 // aggregated projected msgs
__device__ int    g_deg[NN];
__device__ int    g_rowptr[NN + 1];
__device__ int    g_wofs[NN];
__device__ int    g_bsum[512];
__device__ int    g_scancnt;
__device__ __align__(16) int2  g_se[NE];          // CSR-sorted (start,end)
__device__ __align__(16) int   g_end[NE];         // CSR-sorted end only (for k_agg)
__device__ __align__(16) float g_gate[NE];

__device__ __forceinline__ void fma4(float4& a, float s, float4 w) {
    a.x += s * w.x; a.y += s * w.y; a.z += s * w.z; a.w += s * w.w;
}
__device__ __forceinline__ float fsig(float z) {
    return __fdividef(1.f, 1.f + __expf(-z));
}
// packed fp32 helpers (Blackwell f32x2)
__device__ __forceinline__ ull pk2(float x, float y) {
    ull r; asm("mov.b64 %0,{%1,%2};" : "=l"(r) : "f"(x), "f"(y)); return r;
}
__device__ __forceinline__ void upk2(float& x, float& y, ull p) {
    asm("mov.b64 {%0,%1},%2;" : "=f"(x), "=f"(y) : "l"(p));
}
__device__ __forceinline__ void ffma2(ull& d, ull a, ull b) {
    asm("fma.rn.f32x2 %0,%1,%2,%0;" : "+l"(d) : "l"(a), "l"(b));
}

// ---------------- counting sort: build CSR by 'start' ----------------
__global__ void k_zero_deg() {
    int i = blockIdx.x * blockDim.x + threadIdx.x;
    if (i < NN) g_deg[i] = 0;
    if (i == 0) g_scancnt = 0;
}
// EPT=4: 4 independent REDs per thread
__global__ void k_hist(const int* __restrict__ start) {
    int i = blockIdx.x * blockDim.x + threadIdx.x;
    if (i >= NE4) return;
    int4 s4 = ((const int4*)start)[i];
    atomicAdd(&g_deg[s4.x], 1);
    atomicAdd(&g_deg[s4.y], 1);
    atomicAdd(&g_deg[s4.z], 1);
    atomicAdd(&g_deg[s4.w], 1);
}
// fused 3-phase scan in one kernel (grid = NB blocks, all co-resident)
__global__ void __launch_bounds__(256) k_scanfused() {
    __shared__ int s[256];
    int t = threadIdx.x, bid = blockIdx.x;
    int i = bid * 256 + t;
    int d = (i < NN) ? g_deg[i] : 0;
    s[t] = d;
    __syncthreads();
    #pragma unroll
    for (int off = 1; off < 256; off <<= 1) {
        int v = (t >= off) ? s[t - off] : 0;
        __syncthreads();
        s[t] += v;
        __syncthreads();
    }
    int incl = s[t];
    if (t == 255) {
        g_bsum[bid] = incl;
        __threadfence();
        atomicAdd(&g_scancnt, 1);
    }
    if (t == 0) {
        while (*((volatile int*)&g_scancnt) < NB) { }
    }
    __syncthreads();
    __threadfence();
    int part = 0;
    for (int j = t; j < bid; j += 256) part += g_bsum[j];
    __syncthreads();
    s[t] = part;
    __syncthreads();
    #pragma unroll
    for (int off = 128; off > 0; off >>= 1) {
        if (t < off) s[t] += s[t + off];
        __syncthreads();
    }
    int base = s[0];
    if (i < NN) {
        int r = base + incl - d;
        g_rowptr[i] = r;
        g_wofs[i]   = r;
    }
    if (i == NN - 1) g_rowptr[NN] = NE;
}
// EPT=4: 4 independent atomic->store chains per thread
__global__ void k_scatter(const int* __restrict__ ei) {
    int i = blockIdx.x * blockDim.x + threadIdx.x;
    if (i >= NE4) return;
    int4 s4 = ((const int4*)ei)[i];
    int4 t4 = ((const int4*)(ei + NE))[i];
    int p0 = atomicAdd(&g_wofs[s4.x], 1);
    int p1 = atomicAdd(&g_wofs[s4.y], 1);
    int p2 = atomicAdd(&g_wofs[s4.z], 1);
    int p3 = atomicAdd(&g_wofs[s4.w], 1);
    g_se[p0] = make_int2(s4.x, t4.x);  g_end[p0] = t4.x;
    g_se[p1] = make_int2(s4.y, t4.y);  g_end[p1] = t4.y;
    g_se[p2] = make_int2(s4.z, t4.z);  g_end[p2] = t4.z;
    g_se[p3] = make_int2(s4.w, t4.w);  g_end[p3] = t4.w;
}

// ---------------- shared helper: per-node A/B/C precompute from hr[20] ----------------
__device__ __forceinline__ void pre_ABC(int n, const float* hr,
                                        const float4* sEW1, const float4* sEb1,
                                        const float4* sCW) {
    float4 a[4], b[4], c[4];
    #pragma unroll
    for (int r = 0; r < 4; r++) {
        a[r] = sEb1[r];
        b[r] = make_float4(0.f, 0.f, 0.f, 0.f);
        c[r] = make_float4(0.f, 0.f, 0.f, 0.f);
    }
    #pragma unroll
    for (int k = 0; k < 19; k++) {
        float hk = hr[k];
        #pragma unroll
        for (int r = 0; r < 4; r++) {
            fma4(a[r], hk, sEW1[k * 4 + r]);
            fma4(b[r], hk, sEW1[(19 + k) * 4 + r]);
            fma4(c[r], hk, sCW[k * 4 + r]);
        }
    }
    #pragma unroll
    for (int r = 0; r < 4; r++) {
        g_A[n * 4 + r] = a[r];
        g_B[n * 4 + r] = b[r];
        g_C[n * 4 + r] = c[r];
    }
}

// ---------------- encoder + pre for iteration 0 ----------------
__global__ void __launch_bounds__(256) k_encodepre(const float* __restrict__ x,
                                                   const float* __restrict__ W,
                                                   const float* __restrict__ b,
                                                   const float* __restrict__ eW1,
                                                   const float* __restrict__ eb1,
                                                   const float* __restrict__ cW) {
    __shared__ float4 sEW1[152], sCW[76], sEb1[4];
    __shared__ float  sW[48], sb[16];
    int tid = threadIdx.x;
    for (int i = tid; i < 152; i += 256) sEW1[i] = ((const float4*)eW1)[i];
    for (int i = tid; i < 76;  i += 256) sCW[i]  = ((const float4*)cW)[i];
    if (tid < 4)  sEb1[tid] = ((const float4*)eb1)[tid];
    if (tid >= 32 && tid < 80) sW[tid - 32] = W[tid - 32];
    if (tid >= 80 && tid < 96) sb[tid - 80] = b[tid - 80];
    __syncthreads();

    int n = blockIdx.x * 256 + tid;
    if (n >= NN) return;
    float x0 = x[3 * n], x1 = x[3 * n + 1], x2 = x[3 * n + 2];
    float hr[20];
    #pragma unroll
    for (int j = 0; j < 16; j++)
        hr[j] = sb[j] + x0 * sW[j] + x1 * sW[16 + j] + x2 * sW[32 + j];
    hr[16] = x0; hr[17] = x1; hr[18] = x2; hr[19] = 0.f;
    float4* hw = (float4*)(g_h + n * HP);
    #pragma unroll
    for (int r = 0; r < 5; r++)
        hw[r] = make_float4(hr[4*r], hr[4*r+1], hr[4*r+2], hr[4*r+3]);
    pre_ABC(n, hr, sEW1, sEb1, sCW);
}

// ---------------- edge kernel (edge-parallel, EPT=2, packed f32x2 layer-2) ----------------
__global__ void __launch_bounds__(256) k_edge(const float* __restrict__ W2,
                                              const float* __restrict__ b2,
                                              const float* __restrict__ W3,
                                              const float* __restrict__ b3) {
    __shared__ float4 sW2[64], sb2[4], sW3[4];
    __shared__ float  sb3;
    int tid = threadIdx.x;
    if (tid < 64) sW2[tid] = ((const float4*)W2)[tid];
    else if (tid < 68) sb2[tid - 64] = ((const float4*)b2)[tid - 64];
    else if (tid < 72) sW3[tid - 68] = ((const float4*)W3)[tid - 68];
    else if (tid == 72) sb3 = b3[0];
    __syncthreads();

    int g = blockIdx.x * blockDim.x + tid;   // pair index
    if (g >= NE / 2) return;
    int4 p = ((const int4*)g_se)[g];
    int s0 = p.x, t0 = p.y, s1 = p.z, t1 = p.w;

    float h1a[16], h1b[16];
    #pragma unroll
    for (int r = 0; r < 4; r++) {
        float4 av = g_A[s0 * 4 + r], bv = g_B[t0 * 4 + r];
        h1a[4*r]   = fmaxf(av.x + bv.x, 0.f);
        h1a[4*r+1] = fmaxf(av.y + bv.y, 0.f);
        h1a[4*r+2] = fmaxf(av.z + bv.z, 0.f);
        h1a[4*r+3] = fmaxf(av.w + bv.w, 0.f);
        float4 aw = g_A[s1 * 4 + r], bw = g_B[t1 * 4 + r];
        h1b[4*r]   = fmaxf(aw.x + bw.x, 0.f);
        h1b[4*r+1] = fmaxf(aw.y + bw.y, 0.f);
        h1b[4*r+2] = fmaxf(aw.z + bw.z, 0.f);
        h1b[4*r+3] = fmaxf(aw.w + bw.w, 0.f);
    }

    // layer2 packed: acc[j] = (h2[2j], h2[2j+1]) for each edge
    const ull* sW2p = (const ull*)sW2;
    const ull* sb2p = (const ull*)sb2;
    ull acca[8], accb[8];
    #pragma unroll
    for (int j = 0; j < 8; j++) {
        ull bp = sb2p[j];
        acca[j] = bp;
        accb[j] = bp;
    }
    #pragma unroll
    for (int k = 0; k < 16; k++) {
        ull xa2 = pk2(h1a[k], h1a[k]);
        ull xb2 = pk2(h1b[k], h1b[k]);
        #pragma unroll
        for (int j = 0; j < 8; j++) {
            ull w = sW2p[k * 8 + j];
            ffma2(acca[j], xa2, w);
            ffma2(accb[j], xb2, w);
        }
    }

    const float* sW3f = (const float*)sW3;
    float za = sb3, zb = sb3;
    #pragma unroll
    for (int j = 0; j < 8; j++) {
        float w0 = sW3f[2*j], w1 = sW3f[2*j+1];
        float x0, x1;
        upk2(x0, x1, acca[j]);
        za += fmaxf(x0, 0.f) * w0 + fmaxf(x1, 0.f) * w1;
        upk2(x0, x1, accb[j]);
        zb += fmaxf(x0, 0.f) * w0 + fmaxf(x1, 0.f) * w1;
    }
    float ga = fsig(fmaxf(za, 0.f));
    float gb = fsig(fmaxf(zb, 0.f));
    ((float2*)g_gate)[g] = make_float2(ga, gb);
}

// ---------------- aggregation: macc[s] = sum gate * C[end]  (CSR, no atomics) ----------------
// 2-way unrolled: independent load pairs double MLP on the end->C chain.
__global__ void k_agg() {
    int tid = blockIdx.x * blockDim.x + threadIdx.x;
    if (tid >= NN * 4) return;
    int n = tid >> 2, q = tid & 3;
    int lo = g_rowptr[n], hi = g_rowptr[n + 1];
    float4 acc = make_float4(0.f, 0.f, 0.f, 0.f);
    int j = lo;
    for (; j + 1 < hi; j += 2) {
        int t0 = g_end[j],     t1 = g_end[j + 1];
        float g0 = g_gate[j],  g1 = g_gate[j + 1];
        float4 c0 = g_C[t0 * 4 + q], c1 = g_C[t1 * 4 + q];
        fma4(acc, g0, c0);
        fma4(acc, g1, c1);
    }
    if (j < hi) {
        int t = g_end[j];
        fma4(acc, g_gate[j], g_C[t * 4 + q]);
    }
    g_macc[n * 4 + q] = acc;
}

// ---------------- node update, fused with next-iteration A/B/C precompute ----------------
__global__ void __launch_bounds__(256) k_postpre(const float* __restrict__ W1,
                                                 const float* __restrict__ b1,
                                                 const float* __restrict__ W2,
                                                 const float* __restrict__ b2,
                                                 const float* __restrict__ W3,
                                                 const float* __restrict__ b3,
                                                 const float* __restrict__ x,
                                                 float* __restrict__ out,
                                                 int last,
                                                 const float* __restrict__ nEW1,
                                                 const float* __restrict__ nEb1,
                                                 const float* __restrict__ nCW) {
    __shared__ float4 sW1[76], sW2v[64], sW3v[64], sb1[4], sb2v[4], sb3arr[4];
    __shared__ float4 sEW1[152], sCW[76], sEb1[4];
    __shared__ float  sb3s;
    int tid = threadIdx.x;
    for (int i = tid; i < 76; i += 256) sW1[i]  = ((const float4*)W1)[i];
    for (int i = tid; i < 64; i += 256) sW2v[i] = ((const float4*)W2)[i];
    int nW3 = last ? 4 : 64;
    for (int i = tid; i < nW3; i += 256) sW3v[i] = ((const float4*)W3)[i];
    if (!last) {
        for (int i = tid; i < 152; i += 256) sEW1[i] = ((const float4*)nEW1)[i];
        for (int i = tid; i < 76;  i += 256) sCW[i]  = ((const float4*)nCW)[i];
        if (tid >= 16 && tid < 20) sEb1[tid - 16] = ((const float4*)nEb1)[tid - 16];
    }
    if (tid < 4) sb1[tid] = ((const float4*)b1)[tid];
    else if (tid < 8) sb2v[tid - 4] = ((const float4*)b2)[tid - 4];
    else if (tid < 12) {
        if (!last) sb3arr[tid - 8] = ((const float4*)b3)[tid - 8];
        else if (tid == 8) sb3s = b3[0];
    }
    __syncthreads();

    int n = blockIdx.x * 256 + tid;
    if (n >= NN) return;
    float hr[20];
    const float4* h4 = (const float4*)g_h + n * 5;
    #pragma unroll
    for (int r = 0; r < 5; r++) {
        float4 v = h4[r];
        hr[4*r] = v.x; hr[4*r+1] = v.y; hr[4*r+2] = v.z; hr[4*r+3] = v.w;
    }
    float4 l1v[4];
    #pragma unroll
    for (int r = 0; r < 4; r++) {
        float4 mm = g_macc[n * 4 + r], bv = sb1[r];
        l1v[r] = make_float4(mm.x + bv.x, mm.y + bv.y, mm.z + bv.z, mm.w + bv.w);
    }
    #pragma unroll
    for (int k = 0; k < 19; k++) {
        float hk = hr[k];
        #pragma unroll
        for (int r = 0; r < 4; r++) fma4(l1v[r], hk, sW1[k * 4 + r]);
    }
    float l1[16];
    #pragma unroll
    for (int r = 0; r < 4; r++) {
        l1[4*r]   = fmaxf(l1v[r].x, 0.f);
        l1[4*r+1] = fmaxf(l1v[r].y, 0.f);
        l1[4*r+2] = fmaxf(l1v[r].z, 0.f);
        l1[4*r+3] = fmaxf(l1v[r].w, 0.f);
    }
    float4 l2v[4];
    #pragma unroll
    for (int r = 0; r < 4; r++) l2v[r] = sb2v[r];
    #pragma unroll
    for (int k = 0; k < 16; k++) {
        float xk = l1[k];
        #pragma unroll
        for (int r = 0; r < 4; r++) fma4(l2v[r], xk, sW2v[k * 4 + r]);
    }
    float l2[16];
    #pragma unroll
    for (int r = 0; r < 4; r++) {
        l2[4*r]   = fmaxf(l2v[r].x, 0.f);
        l2[4*r+1] = fmaxf(l2v[r].y, 0.f);
        l2[4*r+2] = fmaxf(l2v[r].z, 0.f);
        l2[4*r+3] = fmaxf(l2v[r].w, 0.f);
    }
    if (last) {
        float z = sb3s;
        #pragma unroll
        for (int r = 0; r < 4; r++) {
            float4 w = sW3v[r];
            z += l2[4*r] * w.x + l2[4*r+1] * w.y + l2[4*r+2] * w.z + l2[4*r+3] * w.w;
        }
        out[n] = fsig(z);
        return;
    }
    float4 l3v[4];
    #pragma unroll
    for (int r = 0; r < 4; r++) l3v[r] = sb3arr[r];
    #pragma unroll
    for (int k = 0; k < 16; k++) {
        float xk = l2[k];
        #pragma unroll
        for (int r = 0; r < 4; r++) fma4(l3v[r], xk, sW3v[k * 4 + r]);
    }
    float hn[20];
    #pragma unroll
    for (int r = 0; r < 4; r++) {
        hn[4*r]   = fmaxf(l3v[r].x, 0.f) + hr[4*r];
        hn[4*r+1] = fmaxf(l3v[r].y, 0.f) + hr[4*r+1];
        hn[4*r+2] = fmaxf(l3v[r].z, 0.f) + hr[4*r+2];
        hn[4*r+3] = fmaxf(l3v[r].w, 0.f) + hr[4*r+3];
    }
    hn[16] = x[3*n]     + hr[16];
    hn[17] = x[3*n + 1] + hr[17];
    hn[18] = x[3*n + 2] + hr[18];
    hn[19] = 0.f;
    float4* hw = (float4*)(g_h + n * HP);
    #pragma unroll
    for (int r = 0; r < 5; r++)
        hw[r] = make_float4(hn[4*r], hn[4*r+1], hn[4*r+2], hn[4*r+3]);
    pre_ABC(n, hn, sEW1, sEb1, sCW);
}

// ---------------- launch ----------------
extern "C" void kernel_launch(void* const* d_in, const int* in_sizes, int n_in,
                              void* d_out, int out_size) {
    const float* x    = (const float*)d_in[0];
    const int*   ei   = (const int*)  d_in[1];
    const float* encW = (const float*)d_in[2];
    const float* encb = (const float*)d_in[3];
    const float* eW1  = (const float*)d_in[4];
    const float* eb1  = (const float*)d_in[5];
    const float* eW2  = (const float*)d_in[6];
    const float* eb2  = (const float*)d_in[7];
    const float* eW3  = (const float*)d_in[8];
    const float* eb3  = (const float*)d_in[9];
    const float* nW1  = (const float*)d_in[10];
    const float* nb1  = (const float*)d_in[11];
    const float* nW2  = (const float*)d_in[12];
    const float* nb2  = (const float*)d_in[13];
    const float* nW3  = (const float*)d_in[14];
    const float* nb3  = (const float*)d_in[15];
    const float* oW1  = (const float*)d_in[16];
    const float* ob1  = (const float*)d_in[17];
    const float* oW2  = (const float*)d_in[18];
    const float* ob2  = (const float*)d_in[19];
    const float* oW3  = (const float*)d_in[20];
    const float* ob3  = (const float*)d_in[21];
    float* out = (float*)d_out;

    const int B = 256;
    k_zero_deg <<<NB, B>>>();
    k_hist     <<<(NE4 + B - 1) / B, B>>>(ei);
    k_scanfused<<<NB, B>>>();
    k_scatter  <<<(NE4 + B - 1) / B, B>>>(ei);
    k_encodepre<<<NB, B>>>(x, encW, encb, eW1, eb1, nW1 + 19 * 16);

    for (int i = 0; i < 3; i++) {
        k_edge<<<(NE / 2 + B - 1) / B, B>>>(eW2 + i * 256, eb2 + i * 16,
                                            eW3 + i * 16, eb3 + i);
        k_agg <<<(NN * 4 + B - 1) / B, B>>>();
        if (i < 2) {
            const float* nextCW = (i + 1 < 2) ? (nW1 + (i + 1) * 608 + 19 * 16)
                                              : (oW1 + 19 * 16);
            k_postpre<<<NB, B>>>(nW1 + i * 608, nb1 + i * 16,
                                 nW2 + i * 256, nb2 + i * 16,
                                 nW3 + i * 256, nb3 + i * 16,
                                 x, out, 0,
                                 eW1 + (i + 1) * 608, eb1 + (i + 1) * 16, nextCW);
        } else {
            k_postpre<<<NB, B>>>(oW1, ob1, oW2, ob2, oW3, ob3,
                                 x, out, 1, eW1, eb1, oW1 + 19 * 16);
        }
    }
}

// round 12
// speedup vs baseline: 1.0277x; 1.0277x over previous
#include <cuda_runtime.h>

#define NN 100000
#define NE 1600000
#define HP 20                 // padded node feature width (19 used, [19]=0)
#define NB 391                // ceil(NN/256)
#define NE4 (NE / 4)          // 400000 int4 records exactly

typedef unsigned long long ull;

// ---------------- device scratch (static; no allocations) ----------------
__device__ __align__(16) float  g_h[NN * HP];     // node state [N,20]
__device__ float4 g_A[NN * 4];                    // h @ eW1_top + eb1
__device__ float4 g_B[NN * 4];                    // h @ eW1_bot
__device__ float4 g_C[NN * 4];                    // h @ msgW1_bot (node/out)
__device__ float4 g_macc[NN * 4];                 // aggregated projected msgs
__device__ int    g_deg[NN];
__device__ int    g_rowptr[NN + 1];
__device__ int    g_wofs[NN];
__device__ int    g_bsum[512];
__device__ int    g_scancnt;
__device__ __align__(16) int2  g_se[NE];          // CSR-sorted (start,end)
__device__ __align__(16) float g_gate[NE];

__device__ __forceinline__ void fma4(float4& a, float s, float4 w) {
    a.x += s * w.x; a.y += s * w.y; a.z += s * w.z; a.w += s * w.w;
}
__device__ __forceinline__ float fsig(float z) {
    return __fdividef(1.f, 1.f + __expf(-z));
}
// packed fp32 helpers (Blackwell f32x2)
__device__ __forceinline__ ull pk2(float x, float y) {
    ull r; asm("mov.b64 %0,{%1,%2};" : "=l"(r) : "f"(x), "f"(y)); return r;
}
__device__ __forceinline__ void upk2(float& x, float& y, ull p) {
    asm("mov.b64 {%0,%1},%2;" : "=f"(x), "=f"(y) : "l"(p));
}
__device__ __forceinline__ void ffma2(ull& d, ull a, ull b) {
    asm("fma.rn.f32x2 %0,%1,%2,%0;" : "+l"(d) : "l"(a), "l"(b));
}

// ---------------- counting sort: build CSR by 'start' ----------------
__global__ void k_zero_deg() {
    int i = blockIdx.x * blockDim.x + threadIdx.x;
    if (i < NN) g_deg[i] = 0;
    if (i == 0) g_scancnt = 0;
}
// EPT=4: 4 independent REDs per thread (measured win in R11)
__global__ void k_hist(const int* __restrict__ start) {
    int i = blockIdx.x * blockDim.x + threadIdx.x;
    if (i >= NE4) return;
    int4 s4 = ((const int4*)start)[i];
    atomicAdd(&g_deg[s4.x], 1);
    atomicAdd(&g_deg[s4.y], 1);
    atomicAdd(&g_deg[s4.z], 1);
    atomicAdd(&g_deg[s4.w], 1);
}
// fused 3-phase scan in one kernel (grid = NB blocks, all co-resident)
__global__ void __launch_bounds__(256) k_scanfused() {
    __shared__ int s[256];
    int t = threadIdx.x, bid = blockIdx.x;
    int i = bid * 256 + t;
    int d = (i < NN) ? g_deg[i] : 0;
    s[t] = d;
    __syncthreads();
    #pragma unroll
    for (int off = 1; off < 256; off <<= 1) {
        int v = (t >= off) ? s[t - off] : 0;
        __syncthreads();
        s[t] += v;
        __syncthreads();
    }
    int incl = s[t];
    if (t == 255) {
        g_bsum[bid] = incl;
        __threadfence();
        atomicAdd(&g_scancnt, 1);
    }
    if (t == 0) {
        while (*((volatile int*)&g_scancnt) < NB) { }
    }
    __syncthreads();
    __threadfence();
    int part = 0;
    for (int j = t; j < bid; j += 256) part += g_bsum[j];
    __syncthreads();
    s[t] = part;
    __syncthreads();
    #pragma unroll
    for (int off = 128; off > 0; off >>= 1) {
        if (t < off) s[t] += s[t + off];
        __syncthreads();
    }
    int base = s[0];
    if (i < NN) {
        int r = base + incl - d;
        g_rowptr[i] = r;
        g_wofs[i]   = r;
    }
    if (i == NN - 1) g_rowptr[NN] = NE;
}
// EPT=1 (R10 form — EPT=4 + extra array measured 12µs slower in R11)
__global__ void k_scatter(const int* __restrict__ ei) {
    int e = blockIdx.x * blockDim.x + threadIdx.x;
    if (e < NE) {
        int s = ei[e], t = ei[NE + e];
        int pos = atomicAdd(&g_wofs[s], 1);
        g_se[pos] = make_int2(s, t);
    }
}

// ---------------- shared helper: per-node A/B/C precompute from hr[20] ----------------
__device__ __forceinline__ void pre_ABC(int n, const float* hr,
                                        const float4* sEW1, const float4* sEb1,
                                        const float4* sCW) {
    float4 a[4], b[4], c[4];
    #pragma unroll
    for (int r = 0; r < 4; r++) {
        a[r] = sEb1[r];
        b[r] = make_float4(0.f, 0.f, 0.f, 0.f);
        c[r] = make_float4(0.f, 0.f, 0.f, 0.f);
    }
    #pragma unroll
    for (int k = 0; k < 19; k++) {
        float hk = hr[k];
        #pragma unroll
        for (int r = 0; r < 4; r++) {
            fma4(a[r], hk, sEW1[k * 4 + r]);
            fma4(b[r], hk, sEW1[(19 + k) * 4 + r]);
            fma4(c[r], hk, sCW[k * 4 + r]);
        }
    }
    #pragma unroll
    for (int r = 0; r < 4; r++) {
        g_A[n * 4 + r] = a[r];
        g_B[n * 4 + r] = b[r];
        g_C[n * 4 + r] = c[r];
    }
}

// ---------------- encoder + pre for iteration 0 ----------------
__global__ void __launch_bounds__(256) k_encodepre(const float* __restrict__ x,
                                                   const float* __restrict__ W,
                                                   const float* __restrict__ b,
                                                   const float* __restrict__ eW1,
                                                   const float* __restrict__ eb1,
                                                   const float* __restrict__ cW) {
    __shared__ float4 sEW1[152], sCW[76], sEb1[4];
    __shared__ float  sW[48], sb[16];
    int tid = threadIdx.x;
    for (int i = tid; i < 152; i += 256) sEW1[i] = ((const float4*)eW1)[i];
    for (int i = tid; i < 76;  i += 256) sCW[i]  = ((const float4*)cW)[i];
    if (tid < 4)  sEb1[tid] = ((const float4*)eb1)[tid];
    if (tid >= 32 && tid < 80) sW[tid - 32] = W[tid - 32];
    if (tid >= 80 && tid < 96) sb[tid - 80] = b[tid - 80];
    __syncthreads();

    int n = blockIdx.x * 256 + tid;
    if (n >= NN) return;
    float x0 = x[3 * n], x1 = x[3 * n + 1], x2 = x[3 * n + 2];
    float hr[20];
    #pragma unroll
    for (int j = 0; j < 16; j++)
        hr[j] = sb[j] + x0 * sW[j] + x1 * sW[16 + j] + x2 * sW[32 + j];
    hr[16] = x0; hr[17] = x1; hr[18] = x2; hr[19] = 0.f;
    float4* hw = (float4*)(g_h + n * HP);
    #pragma unroll
    for (int r = 0; r < 5; r++)
        hw[r] = make_float4(hr[4*r], hr[4*r+1], hr[4*r+2], hr[4*r+3]);
    pre_ABC(n, hr, sEW1, sEb1, sCW);
}

// ---------------- edge kernel (edge-parallel, EPT=2, packed f32x2 layer-2) ----------------
__global__ void __launch_bounds__(256) k_edge(const float* __restrict__ W2,
                                              const float* __restrict__ b2,
                                              const float* __restrict__ W3,
                                              const float* __restrict__ b3) {
    __shared__ float4 sW2[64], sb2[4], sW3[4];
    __shared__ float  sb3;
    int tid = threadIdx.x;
    if (tid < 64) sW2[tid] = ((const float4*)W2)[tid];
    else if (tid < 68) sb2[tid - 64] = ((const float4*)b2)[tid - 64];
    else if (tid < 72) sW3[tid - 68] = ((const float4*)W3)[tid - 68];
    else if (tid == 72) sb3 = b3[0];
    __syncthreads();

    int g = blockIdx.x * blockDim.x + tid;   // pair index
    if (g >= NE / 2) return;
    int4 p = ((const int4*)g_se)[g];
    int s0 = p.x, t0 = p.y, s1 = p.z, t1 = p.w;

    float h1a[16], h1b[16];
    #pragma unroll
    for (int r = 0; r < 4; r++) {
        float4 av = g_A[s0 * 4 + r], bv = g_B[t0 * 4 + r];
        h1a[4*r]   = fmaxf(av.x + bv.x, 0.f);
        h1a[4*r+1] = fmaxf(av.y + bv.y, 0.f);
        h1a[4*r+2] = fmaxf(av.z + bv.z, 0.f);
        h1a[4*r+3] = fmaxf(av.w + bv.w, 0.f);
        float4 aw = g_A[s1 * 4 + r], bw = g_B[t1 * 4 + r];
        h1b[4*r]   = fmaxf(aw.x + bw.x, 0.f);
        h1b[4*r+1] = fmaxf(aw.y + bw.y, 0.f);
        h1b[4*r+2] = fmaxf(aw.z + bw.z, 0.f);
        h1b[4*r+3] = fmaxf(aw.w + bw.w, 0.f);
    }

    // layer2 packed: acc[j] = (h2[2j], h2[2j+1]) for each edge
    const ull* sW2p = (const ull*)sW2;
    const ull* sb2p = (const ull*)sb2;
    ull acca[8], accb[8];
    #pragma unroll
    for (int j = 0; j < 8; j++) {
        ull bp = sb2p[j];
        acca[j] = bp;
        accb[j] = bp;
    }
    #pragma unroll
    for (int k = 0; k < 16; k++) {
        ull xa2 = pk2(h1a[k], h1a[k]);
        ull xb2 = pk2(h1b[k], h1b[k]);
        #pragma unroll
        for (int j = 0; j < 8; j++) {
            ull w = sW2p[k * 8 + j];
            ffma2(acca[j], xa2, w);
            ffma2(accb[j], xb2, w);
        }
    }

    const float* sW3f = (const float*)sW3;
    float za = sb3, zb = sb3;
    #pragma unroll
    for (int j = 0; j < 8; j++) {
        float w0 = sW3f[2*j], w1 = sW3f[2*j+1];
        float x0, x1;
        upk2(x0, x1, acca[j]);
        za += fmaxf(x0, 0.f) * w0 + fmaxf(x1, 0.f) * w1;
        upk2(x0, x1, accb[j]);
        zb += fmaxf(x0, 0.f) * w0 + fmaxf(x1, 0.f) * w1;
    }
    float ga = fsig(fmaxf(za, 0.f));
    float gb = fsig(fmaxf(zb, 0.f));
    ((float2*)g_gate)[g] = make_float2(ga, gb);
}

// ---------------- aggregation: macc[s] = sum gate * C[end]  (CSR, no atomics) ----------------
// 2-way unrolled: independent load pairs double MLP on the end->C chain (measured win in R11).
__global__ void k_agg() {
    int tid = blockIdx.x * blockDim.x + threadIdx.x;
    if (tid >= NN * 4) return;
    int n = tid >> 2, q = tid & 3;
    int lo = g_rowptr[n], hi = g_rowptr[n + 1];
    float4 acc = make_float4(0.f, 0.f, 0.f, 0.f);
    int j = lo;
    for (; j + 1 < hi; j += 2) {
        int t0 = g_se[j].y,    t1 = g_se[j + 1].y;
        float g0 = g_gate[j],  g1 = g_gate[j + 1];
        float4 c0 = g_C[t0 * 4 + q], c1 = g_C[t1 * 4 + q];
        fma4(acc, g0, c0);
        fma4(acc, g1, c1);
    }
    if (j < hi) {
        int t = g_se[j].y;
        fma4(acc, g_gate[j], g_C[t * 4 + q]);
    }
    g_macc[n * 4 + q] = acc;
}

// ---------------- node update, fused with next-iteration A/B/C precompute ----------------
__global__ void __launch_bounds__(256) k_postpre(const float* __restrict__ W1,
                                                 const float* __restrict__ b1,
                                                 const float* __restrict__ W2,
                                                 const float* __restrict__ b2,
                                                 const float* __restrict__ W3,
                                                 const float* __restrict__ b3,
                                                 const float* __restrict__ x,
                                                 float* __restrict__ out,
                                                 int last,
                                                 const float* __restrict__ nEW1,
                                                 const float* __restrict__ nEb1,
                                                 const float* __restrict__ nCW) {
    __shared__ float4 sW1[76], sW2v[64], sW3v[64], sb1[4], sb2v[4], sb3arr[4];
    __shared__ float4 sEW1[152], sCW[76], sEb1[4];
    __shared__ float  sb3s;
    int tid = threadIdx.x;
    for (int i = tid; i < 76; i += 256) sW1[i]  = ((const float4*)W1)[i];
    for (int i = tid; i < 64; i += 256) sW2v[i] = ((const float4*)W2)[i];
    int nW3 = last ? 4 : 64;
    for (int i = tid; i < nW3; i += 256) sW3v[i] = ((const float4*)W3)[i];
    if (!last) {
        for (int i = tid; i < 152; i += 256) sEW1[i] = ((const float4*)nEW1)[i];
        for (int i = tid; i < 76;  i += 256) sCW[i]  = ((const float4*)nCW)[i];
        if (tid >= 16 && tid < 20) sEb1[tid - 16] = ((const float4*)nEb1)[tid - 16];
    }
    if (tid < 4) sb1[tid] = ((const float4*)b1)[tid];
    else if (tid < 8) sb2v[tid - 4] = ((const float4*)b2)[tid - 4];
    else if (tid < 12) {
        if (!last) sb3arr[tid - 8] = ((const float4*)b3)[tid - 8];
        else if (tid == 8) sb3s = b3[0];
    }
    __syncthreads();

    int n = blockIdx.x * 256 + tid;
    if (n >= NN) return;
    float hr[20];
    const float4* h4 = (const float4*)g_h + n * 5;
    #pragma unroll
    for (int r = 0; r < 5; r++) {
        float4 v = h4[r];
        hr[4*r] = v.x; hr[4*r+1] = v.y; hr[4*r+2] = v.z; hr[4*r+3] = v.w;
    }
    float4 l1v[4];
    #pragma unroll
    for (int r = 0; r < 4; r++) {
        float4 mm = g_macc[n * 4 + r], bv = sb1[r];
        l1v[r] = make_float4(mm.x + bv.x, mm.y + bv.y, mm.z + bv.z, mm.w + bv.w);
    }
    #pragma unroll
    for (int k = 0; k < 19; k++) {
        float hk = hr[k];
        #pragma unroll
        for (int r = 0; r < 4; r++) fma4(l1v[r], hk, sW1[k * 4 + r]);
    }
    float l1[16];
    #pragma unroll
    for (int r = 0; r < 4; r++) {
        l1[4*r]   = fmaxf(l1v[r].x, 0.f);
        l1[4*r+1] = fmaxf(l1v[r].y, 0.f);
        l1[4*r+2] = fmaxf(l1v[r].z, 0.f);
        l1[4*r+3] = fmaxf(l1v[r].w, 0.f);
    }
    float4 l2v[4];
    #pragma unroll
    for (int r = 0; r < 4; r++) l2v[r] = sb2v[r];
    #pragma unroll
    for (int k = 0; k < 16; k++) {
        float xk = l1[k];
        #pragma unroll
        for (int r = 0; r < 4; r++) fma4(l2v[r], xk, sW2v[k * 4 + r]);
    }
    float l2[16];
    #pragma unroll
    for (int r = 0; r < 4; r++) {
        l2[4*r]   = fmaxf(l2v[r].x, 0.f);
        l2[4*r+1] = fmaxf(l2v[r].y, 0.f);
        l2[4*r+2] = fmaxf(l2v[r].z, 0.f);
        l2[4*r+3] = fmaxf(l2v[r].w, 0.f);
    }
    if (last) {
        float z = sb3s;
        #pragma unroll
        for (int r = 0; r < 4; r++) {
            float4 w = sW3v[r];
            z += l2[4*r] * w.x + l2[4*r+1] * w.y + l2[4*r+2] * w.z + l2[4*r+3] * w.w;
        }
        out[n] = fsig(z);
        return;
    }
    float4 l3v[4];
    #pragma unroll
    for (int r = 0; r < 4; r++) l3v[r] = sb3arr[r];
    #pragma unroll
    for (int k = 0; k < 16; k++) {
        float xk = l2[k];
        #pragma unroll
        for (int r = 0; r < 4; r++) fma4(l3v[r], xk, sW3v[k * 4 + r]);
    }
    float hn[20];
    #pragma unroll
    for (int r = 0; r < 4; r++) {
        hn[4*r]   = fmaxf(l3v[r].x, 0.f) + hr[4*r];
        hn[4*r+1] = fmaxf(l3v[r].y, 0.f) + hr[4*r+1];
        hn[4*r+2] = fmaxf(l3v[r].z, 0.f) + hr[4*r+2];
        hn[4*r+3] = fmaxf(l3v[r].w, 0.f) + hr[4*r+3];
    }
    hn[16] = x[3*n]     + hr[16];
    hn[17] = x[3*n + 1] + hr[17];
    hn[18] = x[3*n + 2] + hr[18];
    hn[19] = 0.f;
    float4* hw = (float4*)(g_h + n * HP);
    #pragma unroll
    for (int r = 0; r < 5; r++)
        hw[r] = make_float4(hn[4*r], hn[4*r+1], hn[4*r+2], hn[4*r+3]);
    pre_ABC(n, hn, sEW1, sEb1, sCW);
}

// ---------------- launch ----------------
extern "C" void kernel_launch(void* const* d_in, const int* in_sizes, int n_in,
                              void* d_out, int out_size) {
    const float* x    = (const float*)d_in[0];
    const int*   ei   = (const int*)  d_in[1];
    const float* encW = (const float*)d_in[2];
    const float* encb = (const float*)d_in[3];
    const float* eW1  = (const float*)d_in[4];
    const float* eb1  = (const float*)d_in[5];
    const float* eW2  = (const float*)d_in[6];
    const float* eb2  = (const float*)d_in[7];
    const float* eW3  = (const float*)d_in[8];
    const float* eb3  = (const float*)d_in[9];
    const float* nW1  = (const float*)d_in[10];
    const float* nb1  = (const float*)d_in[11];
    const float* nW2  = (const float*)d_in[12];
    const float* nb2  = (const float*)d_in[13];
    const float* nW3  = (const float*)d_in[14];
    const float* nb3  = (const float*)d_in[15];
    const float* oW1  = (const float*)d_in[16];
    const float* ob1  = (const float*)d_in[17];
    const float* oW2  = (const float*)d_in[18];
    const float* ob2  = (const float*)d_in[19];
    const float* oW3  = (const float*)d_in[20];
    const float* ob3  = (const float*)d_in[21];
    float* out = (float*)d_out;

    const int B = 256;
    k_zero_deg <<<NB, B>>>();
    k_hist     <<<(NE4 + B - 1) / B, B>>>(ei);
    k_scanfused<<<NB, B>>>();
    k_scatter  <<<(NE + B - 1) / B, B>>>(ei);
    k_encodepre<<<NB, B>>>(x, encW, encb, eW1, eb1, nW1 + 19 * 16);

    for (int i = 0; i < 3; i++) {
        k_edge<<<(NE / 2 + B - 1) / B, B>>>(eW2 + i * 256, eb2 + i * 16,
                                            eW3 + i * 16, eb3 + i);
        k_agg <<<(NN * 4 + B - 1) / B, B>>>();
        if (i < 2) {
            const float* nextCW = (i + 1 < 2) ? (nW1 + (i + 1) * 608 + 19 * 16)
                                              : (oW1 + 19 * 16);
            k_postpre<<<NB, B>>>(nW1 + i * 608, nb1 + i * 16,
                                 nW2 + i * 256, nb2 + i * 16,
                                 nW3 + i * 256, nb3 + i * 16,
                                 x, out, 0,
                                 eW1 + (i + 1) * 608, eb1 + (i + 1) * 16, nextCW);
        } else {
            k_postpre<<<NB, B>>>(oW1, ob1, oW2, ob2, oW3, ob3,
                                 x, out, 1, eW1, eb1, oW1 + 19 * 16);
        }
    }
}